// round 5
// baseline (speedup 1.0000x reference)
#include <cuda_runtime.h>

#define IN_SZ   64
#define HID     128
#define NWARP   16
#define NTHREADS 512

typedef unsigned long long ull;

// acc(f32x2) += w(f32x2) * m(f32x2)   -> SASS FFMA2 (only reachable via PTX)
__device__ __forceinline__ void fma2(ull &a, ull w, ull m) {
    asm("fma.rn.f32x2 %0, %1, %2, %0;" : "+l"(a) : "l"(w), "l"(m));
}

__device__ __forceinline__ float2 unpack2(ull v) {
    float2 r;
    asm("mov.b64 {%0, %1}, %2;" : "=f"(r.x), "=f"(r.y) : "l"(v));
    return r;
}

// One dense layer: out_j = tanh(b_j + sum_k Wt[k][j] * in[k]), j = 0..127.
// inB holds K activations duplicated as pairs: inB[2k] == inB[2k+1] == m[k].
// outB receives 128 outputs duplicated the same way (256 floats).
// Each lane computes j = 4*lane .. 4*lane+3.
template<int K>
__device__ __forceinline__ void mlp_layer(const float* __restrict__ sWt,
                                          const float* __restrict__ sB,
                                          const float* __restrict__ inB,
                                          float*       __restrict__ outB,
                                          int lane)
{
    const int j4 = lane * 4;
    ulonglong2 bb = *(const ulonglong2*)(sB + j4);   // {b0,b1},{b2,b3}
    ull a01 = bb.x, a23 = bb.y;
    #pragma unroll 16
    for (int k = 0; k < K; k++) {
        ull mm = *(const ull*)(inB + 2 * k);                       // LDS.64 broadcast
        ulonglong2 w = *(const ulonglong2*)(sWt + k * HID + j4);   // LDS.128
        fma2(a01, w.x, mm);
        fma2(a23, w.y, mm);
    }
    float2 p = unpack2(a01), q = unpack2(a23);
    float h0 = tanhf(p.x), h1 = tanhf(p.y);
    float h2 = tanhf(q.x), h3 = tanhf(q.y);
    *(float4*)(outB + 8 * lane)     = make_float4(h0, h0, h1, h1);
    *(float4*)(outB + 8 * lane + 4) = make_float4(h2, h2, h3, h3);
}

// Shared layout (floats):
//  sW1t : 64*128   = 8192
//  sW2t : 128*128  = 16384
//  sW3t : 128*128  = 16384
//  sB1/sB2/sB3 : 128 each
//  sW4  : 128
//  sB4  : 4 (pad)
//  bufs : NWARP * 512  (per warp: bufA[256] | bufB[256], duplicated activations)
#define SMEM_FLOATS (8192 + 16384 + 16384 + 3*128 + 128 + 4 + NWARP*512)
#define SMEM_BYTES  (SMEM_FLOATS * 4)

__global__ void __launch_bounds__(NTHREADS, 1)
gnn_mlp_kernel(const float* __restrict__ edge_attr,
               const float* __restrict__ W1, const float* __restrict__ b1,
               const float* __restrict__ W2, const float* __restrict__ b2,
               const float* __restrict__ W3, const float* __restrict__ b3,
               const float* __restrict__ W4, const float* __restrict__ b4,
               float* __restrict__ out, int E)
{
    extern __shared__ float smem[];
    float* sW1t = smem;                       // [k][j] k<64
    float* sW2t = sW1t + IN_SZ * HID;         // [k][j] k<128
    float* sW3t = sW2t + HID * HID;
    float* sB1  = sW3t + HID * HID;
    float* sB2  = sB1 + HID;
    float* sB3  = sB2 + HID;
    float* sW4  = sB3 + HID;
    float* sB4  = sW4 + HID;                  // [0] used, padded to 4
    float* bufs = sB4 + 4;

    const int tid = threadIdx.x;

    // Cooperative load + transpose of weights into SMEM.
    for (int i = tid; i < HID * IN_SZ; i += NTHREADS) {
        int j = i / IN_SZ, k = i % IN_SZ;     // W1[j][k], j = out neuron
        sW1t[k * HID + j] = W1[i];
    }
    for (int i = tid; i < HID * HID; i += NTHREADS) {
        int j = i >> 7, k = i & (HID - 1);
        sW2t[k * HID + j] = W2[i];
        sW3t[k * HID + j] = W3[i];
    }
    for (int i = tid; i < HID; i += NTHREADS) {
        sB1[i] = b1[i]; sB2[i] = b2[i]; sB3[i] = b3[i]; sW4[i] = W4[i];
    }
    if (tid == 0) sB4[0] = b4[0];
    __syncthreads();

    const int warp = tid >> 5, lane = tid & 31;
    float* bufA = bufs + warp * 512;
    float* bufB = bufA + 256;
    const float bias4 = sB4[0];

    const int gw     = blockIdx.x * NWARP + warp;
    const int stride = gridDim.x * NWARP;

    int e = gw;
    float2 v = make_float2(0.f, 0.f);
    if (e < E)
        v = *(const float2*)(edge_attr + (size_t)e * IN_SZ + lane * 2);

    for (; e < E; e += stride) {
        // Stage current input (duplicated pairs) and prefetch the next edge.
        *(float4*)(bufA + 4 * lane) = make_float4(v.x, v.x, v.y, v.y);
        int en = e + stride;
        if (en < E)
            v = *(const float2*)(edge_attr + (size_t)en * IN_SZ + lane * 2);
        __syncwarp();

        mlp_layer<IN_SZ>(sW1t, sB1, bufA, bufB, lane);
        __syncwarp();
        mlp_layer<HID>(sW2t, sB2, bufB, bufA, lane);
        __syncwarp();
        mlp_layer<HID>(sW3t, sB3, bufA, bufB, lane);
        __syncwarp();

        // Final layer: 128-dot with W4, warp reduction, sigmoid.
        float4 w4 = *(const float4*)(sW4 + lane * 4);
        float s = w4.x * bufB[8 * lane]
                + w4.y * bufB[8 * lane + 2]
                + w4.z * bufB[8 * lane + 4]
                + w4.w * bufB[8 * lane + 6];
        #pragma unroll
        for (int off = 16; off; off >>= 1)
            s += __shfl_xor_sync(0xFFFFFFFFu, s, off);
        if (lane == 0) {
            float z = s + bias4;
            out[e] = 1.0f / (1.0f + expf(-z));
        }
        __syncwarp();
    }
}

extern "C" void kernel_launch(void* const* d_in, const int* in_sizes, int n_in,
                              void* d_out, int out_size)
{
    // metadata order: x, edge_index, edge_attr, W1, b1, W2, b2, W3, b3, W4, b4
    const float* edge_attr = (const float*)d_in[2];
    const float* W1 = (const float*)d_in[3];
    const float* b1 = (const float*)d_in[4];
    const float* W2 = (const float*)d_in[5];
    const float* b2 = (const float*)d_in[6];
    const float* W3 = (const float*)d_in[7];
    const float* b3 = (const float*)d_in[8];
    const float* W4 = (const float*)d_in[9];
    const float* b4 = (const float*)d_in[10];
    float* out = (float*)d_out;
    const int E = out_size;   // 800000

    cudaFuncSetAttribute(gnn_mlp_kernel,
                         cudaFuncAttributeMaxDynamicSharedMemorySize, SMEM_BYTES);

    int nsm = 148;
    cudaDeviceGetAttribute(&nsm, cudaDevAttrMultiProcessorCount, 0);

    gnn_mlp_kernel<<<nsm, NTHREADS, SMEM_BYTES>>>(
        edge_attr, W1, b1, W2, b2, W3, b3, W4, b4, out, E);
}

// round 7
// speedup vs baseline: 3.3433x; 3.3433x over previous
#include <cuda_runtime.h>
#include <cstdint>

#define NTHREADS 512
#define SROW 132          // At row stride in floats (128 + 4 pad, breaks bank alignment)

// ---- SMEM float-offset layout ----
#define WP1f 0            // 32 kp-rows x 256  (W1 k-pair interleaved)
#define WP2f 8192         // 64 x 256
#define WP3f 24576        // 64 x 256
#define B1f  40960
#define B2f  41088
#define B3f  41216
#define W4f  41344
#define B4f  41472        // 4 floats (1 used)
#define ATf  41476        // 64 x 132 activations
#define SMEM_FLOATS (ATf + 64 * SROW)
#define SMEM_BYTES  (SMEM_FLOATS * 4)   // 199,696 B

typedef unsigned long long ull;

// packed fp32x2 FMA: acc += a * w  (SASS FFMA2; PTX-only form)
__device__ __forceinline__ void fma2(ull &acc, ull a, ull w) {
    asm("fma.rn.f32x2 %0, %1, %2, %0;" : "+l"(acc) : "l"(a), "l"(w));
}
__device__ __forceinline__ float2 unpack2(ull v) {
    float2 r;
    asm("mov.b64 {%0, %1}, %2;" : "=f"(r.x), "=f"(r.y) : "l"(v));
    return r;
}
__device__ __forceinline__ float ex2_apx(float x) {
    float y; asm("ex2.approx.f32 %0, %1;" : "=f"(y) : "f"(x)); return y;
}
__device__ __forceinline__ float rcp_apx(float x) {
    float y; asm("rcp.approx.f32 %0, %1;" : "=f"(y) : "f"(x)); return y;
}
// tanh(x) = 1 - 2/(1 + e^{2x}); MUFU-based, ~1e-6 abs error
__device__ __forceinline__ float tanh_fast(float x) {
    float e = ex2_apx(x * 2.8853900817779268f);   // exp(2x)
    float r = rcp_apx(1.0f + e);
    return fmaf(-2.0f, r, 1.0f);
}
__device__ __forceinline__ float sigmoid_fast(float z) {
    return rcp_apx(1.0f + ex2_apx(z * -1.4426950408889634f));
}

// One layer's K-loop: acc[ee][m] accumulates {even-k, odd-k} partial dots.
// a pair   : At[eb+ee][2kp .. 2kp+1]         (LDS.64, ty-broadcast)
// w pair   : Wp[kp][2*(tx+16m) .. +1]        (LDS.64, conflict-free across tx)
__device__ __forceinline__ void layer_mm(const float* __restrict__ sm, int wbase,
                                         int KP, int eb, int tx, ull acc[2][8])
{
    #pragma unroll
    for (int ee = 0; ee < 2; ee++)
        #pragma unroll
        for (int m = 0; m < 8; m++) acc[ee][m] = 0ull;

    #pragma unroll 2
    for (int kp = 0; kp < KP; kp++) {
        ull a0 = *(const ull*)(sm + ATf + (eb + 0) * SROW + 2 * kp);
        ull a1 = *(const ull*)(sm + ATf + (eb + 1) * SROW + 2 * kp);
        ull w[8];
        #pragma unroll
        for (int m = 0; m < 8; m++)
            w[m] = *(const ull*)(sm + wbase + kp * 256 + 2 * (tx + 16 * m));
        #pragma unroll
        for (int m = 0; m < 8; m++) { fma2(acc[0][m], a0, w[m]); fma2(acc[1][m], a1, w[m]); }
    }
}

__global__ void __launch_bounds__(NTHREADS, 1)
gnn_mlp_rb(const float* __restrict__ EA,
           const float* __restrict__ W1, const float* __restrict__ b1,
           const float* __restrict__ W2, const float* __restrict__ b2,
           const float* __restrict__ W3, const float* __restrict__ b3,
           const float* __restrict__ W4, const float* __restrict__ b4,
           float* __restrict__ out, int E)
{
    extern __shared__ float sm[];
    const int tid = threadIdx.x;
    const int tx  = tid & 15;
    const int tyq = tid >> 4;          // 0..31
    const int eb  = tyq * 2;           // this thread's 2 edges within tile

    // ---- one-time weight prep: k-pair interleave Wp[kp][2j + (k&1)] = W[j][k]
    for (int i = tid; i < 128 * 64; i += NTHREADS) {
        int j = i >> 6, k = i & 63;
        sm[WP1f + (k >> 1) * 256 + 2 * j + (k & 1)] = W1[i];
    }
    for (int i = tid; i < 128 * 128; i += NTHREADS) {
        int j = i >> 7, k = i & 127;
        int d = (k >> 1) * 256 + 2 * j + (k & 1);
        sm[WP2f + d] = W2[i];
        sm[WP3f + d] = W3[i];
    }
    for (int i = tid; i < 128; i += NTHREADS) {
        sm[B1f + i] = b1[i]; sm[B2f + i] = b2[i]; sm[B3f + i] = b3[i];
        sm[W4f + i] = W4[i];
    }
    if (tid == 0) sm[B4f] = b4[0];
    __syncthreads();

    const float b4s = sm[B4f];
    const int NT = (E + 63) >> 6;

    for (int t = blockIdx.x; t < NT; t += gridDim.x) {
        const int tbase = t << 6;
        const bool full = (tbase + 64 <= E);

        // ---- stage 64x64 edge tile into At (coalesced float4) ----
        {
            const float4* g = (const float4*)(EA + ((size_t)tbase << 6));
            #pragma unroll
            for (int r = 0; r < 2; r++) {
                int e = r * 32 + (tid >> 4);
                int c = tid & 15;
                float4 v;
                if (full || tbase + e < E) v = __ldg(g + e * 16 + c);
                else v = make_float4(0.f, 0.f, 0.f, 0.f);
                *(float4*)(sm + ATf + e * SROW + c * 4) = v;
            }
        }
        __syncthreads();

        ull acc[2][8];

        // ---- layer 1 (K=64) ----
        layer_mm(sm, WP1f, 32, eb, tx, acc);
        __syncthreads();                       // all reads of At done
        #pragma unroll
        for (int m = 0; m < 8; m++) {
            int j = tx + 16 * m;
            float bj = sm[B1f + j];
            #pragma unroll
            for (int ee = 0; ee < 2; ee++) {
                float2 p = unpack2(acc[ee][m]);
                sm[ATf + (eb + ee) * SROW + j] = tanh_fast(p.x + p.y + bj);
            }
        }
        __syncthreads();

        // ---- layer 2 (K=128) ----
        layer_mm(sm, WP2f, 64, eb, tx, acc);
        __syncthreads();
        #pragma unroll
        for (int m = 0; m < 8; m++) {
            int j = tx + 16 * m;
            float bj = sm[B2f + j];
            #pragma unroll
            for (int ee = 0; ee < 2; ee++) {
                float2 p = unpack2(acc[ee][m]);
                sm[ATf + (eb + ee) * SROW + j] = tanh_fast(p.x + p.y + bj);
            }
        }
        __syncthreads();

        // ---- layer 3 (K=128) + W4 head, all in registers ----
        layer_mm(sm, WP3f, 64, eb, tx, acc);

        float part0 = 0.f, part1 = 0.f;
        #pragma unroll
        for (int m = 0; m < 8; m++) {
            int j = tx + 16 * m;
            float bj = sm[B3f + j];
            float w4 = sm[W4f + j];
            float2 p0 = unpack2(acc[0][m]);
            float2 p1 = unpack2(acc[1][m]);
            part0 = fmaf(w4, tanh_fast(p0.x + p0.y + bj), part0);
            part1 = fmaf(w4, tanh_fast(p1.x + p1.y + bj), part1);
        }
        // reduce across the 16 tx lanes (lane = tx + 16*(tyq&1): xor<16 stays in half)
        #pragma unroll
        for (int s = 1; s < 16; s <<= 1) {
            part0 += __shfl_xor_sync(0xFFFFFFFFu, part0, s);
            part1 += __shfl_xor_sync(0xFFFFFFFFu, part1, s);
        }
        if (tx == 0) {
            int e0 = tbase + eb;
            if (full || e0     < E) out[e0]     = sigmoid_fast(part0 + b4s);
            if (full || e0 + 1 < E) out[e0 + 1] = sigmoid_fast(part1 + b4s);
        }
        __syncthreads();                       // At free for next tile's staging
    }
}

extern "C" void kernel_launch(void* const* d_in, const int* in_sizes, int n_in,
                              void* d_out, int out_size)
{
    // metadata order: x, edge_index, edge_attr, W1, b1, W2, b2, W3, b3, W4, b4
    const float* EA = (const float*)d_in[2];
    const float* W1 = (const float*)d_in[3];
    const float* b1 = (const float*)d_in[4];
    const float* W2 = (const float*)d_in[5];
    const float* b2 = (const float*)d_in[6];
    const float* W3 = (const float*)d_in[7];
    const float* b3 = (const float*)d_in[8];
    const float* W4 = (const float*)d_in[9];
    const float* b4 = (const float*)d_in[10];
    float* out = (float*)d_out;
    const int E = out_size;   // 800000

    cudaFuncSetAttribute(gnn_mlp_rb,
                         cudaFuncAttributeMaxDynamicSharedMemorySize, SMEM_BYTES);
    int nsm = 148;
    cudaDeviceGetAttribute(&nsm, cudaDevAttrMultiProcessorCount, 0);

    gnn_mlp_rb<<<nsm, NTHREADS, SMEM_BYTES>>>(
        EA, W1, b1, W2, b2, W3, b3, W4, b4, out, E);
}

// round 8
// speedup vs baseline: 4.5888x; 1.3725x over previous
#include <cuda_runtime.h>
#include <cstdint>

#define NTHREADS 512
#define SROW 132           // activation row stride (floats): 128 + 4 pad

// ---- SMEM float-offset layout ----
#define WP1f 0             // 32 kp-rows x 256 floats (j-pair/k-pair interleaved)
#define WP2f 8192          // 64 x 256
#define WP3f 24576         // 64 x 256
#define B1f  40960
#define B2f  41088
#define B3f  41216
#define W4f  41344
#define B4f  41472         // 4 floats (1 used)
#define PPf  41476         // 64 edges x 2 half-partials
#define ATf  41604         // 64 x SROW activations (16B-aligned: 41604%4==0)
#define SMEM_FLOATS (ATf + 64 * SROW)
#define SMEM_BYTES  (SMEM_FLOATS * 4)   // 200,208 B

typedef unsigned long long ull;

// packed fp32x2 FMA (SASS FFMA2; PTX-only form)
__device__ __forceinline__ void fma2(ull &acc, ull a, ull w) {
    asm("fma.rn.f32x2 %0, %1, %2, %0;" : "+l"(acc) : "l"(a), "l"(w));
}
__device__ __forceinline__ float2 unpack2(ull v) {
    float2 r;
    asm("mov.b64 {%0, %1}, %2;" : "=f"(r.x), "=f"(r.y) : "l"(v));
    return r;
}
__device__ __forceinline__ float ex2_apx(float x) {
    float y; asm("ex2.approx.f32 %0, %1;" : "=f"(y) : "f"(x)); return y;
}
__device__ __forceinline__ float rcp_apx(float x) {
    float y; asm("rcp.approx.f32 %0, %1;" : "=f"(y) : "f"(x)); return y;
}
// tanh(x) = 1 - 2/(1+e^{2x});  2 MUFU, ~1e-7 rel err
__device__ __forceinline__ float tanh_fast(float x) {
    float e = ex2_apx(x * 2.8853900817779268f);
    return fmaf(-2.0f, rcp_apx(1.0f + e), 1.0f);
}
__device__ __forceinline__ float sigmoid_fast(float z) {
    return rcp_apx(1.0f + ex2_apx(z * -1.4426950408889634f));
}

// One layer: 8 edges x 2 outputs per thread.
// Weights: lane reads LDS.128 (all-distinct, 512B/warp) giving
//   {W[j0][2kp],W[j0][2kp+1],W[j1][2kp],W[j1][2kp+1]}.
// Activations: LDS.128 broadcast (2 k-pairs).
// acc0[e]/acc1[e] hold {even-k, odd-k} packed partial sums for j0/j1.
template<int KPP>
__device__ __forceinline__ void layer_mm(const float* __restrict__ sm, int wbase,
                                         int arow, int widx,
                                         ull acc0[8], ull acc1[8])
{
    #pragma unroll
    for (int e = 0; e < 8; e++) { acc0[e] = 0ull; acc1[e] = 0ull; }

    #pragma unroll 2
    for (int kpp = 0; kpp < KPP; kpp++) {
        ulonglong2 wA = *(const ulonglong2*)(sm + wbase + (2 * kpp)     * 256 + widx);
        ulonglong2 wB = *(const ulonglong2*)(sm + wbase + (2 * kpp + 1) * 256 + widx);
        #pragma unroll
        for (int e = 0; e < 8; e++) {
            ulonglong2 a = *(const ulonglong2*)(sm + arow + e * SROW + 4 * kpp);
            fma2(acc0[e], a.x, wA.x);
            fma2(acc1[e], a.x, wA.y);
            fma2(acc0[e], a.y, wB.x);
            fma2(acc1[e], a.y, wB.y);
        }
    }
}

// epilogue: tanh(acc + bias) -> At[e][j0..j1]  (STS.64, conflict-free)
__device__ __forceinline__ void epi(float* __restrict__ sm, int bf,
                                    int arow, int jcol,
                                    const ull acc0[8], const ull acc1[8])
{
    float2 bj = *(const float2*)(sm + bf + jcol);
    #pragma unroll
    for (int e = 0; e < 8; e++) {
        float2 p0 = unpack2(acc0[e]);
        float2 p1 = unpack2(acc1[e]);
        float v0 = tanh_fast(p0.x + p0.y + bj.x);
        float v1 = tanh_fast(p1.x + p1.y + bj.y);
        *(float2*)(sm + arow + e * SROW + jcol) = make_float2(v0, v1);
    }
}

__global__ void __launch_bounds__(NTHREADS, 1)
gnn_mlp_v3(const float* __restrict__ EA,
           const float* __restrict__ W1, const float* __restrict__ b1,
           const float* __restrict__ W2, const float* __restrict__ b2,
           const float* __restrict__ W3, const float* __restrict__ b3,
           const float* __restrict__ W4, const float* __restrict__ b4,
           float* __restrict__ out, int E)
{
    extern __shared__ float sm[];
    const int tid  = threadIdx.x;
    const int lane = tid & 31;
    const int warp = tid >> 5;          // 0..15
    const int h    = warp & 1;          // j-half
    const int g    = warp >> 1;         // edge-group 0..7
    const int eb   = g * 8;             // first tile-local edge
    const int jb   = h * 64;
    const int jcol = jb + 2 * lane;     // j0; j1 = jcol+1
    const int widx = (h * 32 + lane) * 4;
    const int arow = ATf + eb * SROW;

    // ---- one-time weight prep: off = kp*256 + (j>>1)*4 + (j&1)*2 + (k&1)
    for (int i = tid; i < 128 * 64; i += NTHREADS) {
        int j = i >> 6, k = i & 63;
        sm[WP1f + (k >> 1) * 256 + (j >> 1) * 4 + (j & 1) * 2 + (k & 1)] = W1[i];
    }
    for (int i = tid; i < 128 * 128; i += NTHREADS) {
        int j = i >> 7, k = i & 127;
        int d = (k >> 1) * 256 + (j >> 1) * 4 + (j & 1) * 2 + (k & 1);
        sm[WP2f + d] = W2[i];
        sm[WP3f + d] = W3[i];
    }
    for (int i = tid; i < 128; i += NTHREADS) {
        sm[B1f + i] = b1[i]; sm[B2f + i] = b2[i]; sm[B3f + i] = b3[i];
        sm[W4f + i] = W4[i];
    }
    if (tid == 0) sm[B4f] = b4[0];
    __syncthreads();

    const float b4s = sm[B4f];
    const int NT = (E + 63) >> 6;

    // staging map: thread covers 2 float4 cells of the 64x16 float4 tile
    const int se0 = (tid >> 4), se1 = 32 + (tid >> 4);
    const int sc  = tid & 15;

    int t = blockIdx.x;
    float4 v0 = make_float4(0.f,0.f,0.f,0.f), v1 = v0;
    if (t < NT) {
        const float4* gsrc = (const float4*)(EA + ((size_t)(t << 6) << 6));
        int tb = t << 6;
        if (tb + se0 < E) v0 = __ldg(gsrc + se0 * 16 + sc);
        if (tb + se1 < E) v1 = __ldg(gsrc + se1 * 16 + sc);
    }

    for (; t < NT; t += gridDim.x) {
        const int tbase = t << 6;

        __syncthreads();                                  // At free
        *(float4*)(sm + ATf + se0 * SROW + sc * 4) = v0;
        *(float4*)(sm + ATf + se1 * SROW + sc * 4) = v1;
        __syncthreads();

        // prefetch next tile into registers (latency hidden behind 3 layers)
        int tn = t + gridDim.x;
        if (tn < NT) {
            const float4* gsrc = (const float4*)(EA + ((size_t)(tn << 6) << 6));
            int tb = tn << 6;
            v0 = (tb + se0 < E) ? __ldg(gsrc + se0 * 16 + sc) : make_float4(0.f,0.f,0.f,0.f);
            v1 = (tb + se1 < E) ? __ldg(gsrc + se1 * 16 + sc) : make_float4(0.f,0.f,0.f,0.f);
        }

        ull acc0[8], acc1[8];

        layer_mm<16>(sm, WP1f, arow, widx, acc0, acc1);   // K=64
        __syncthreads();
        epi(sm, B1f, arow, jcol, acc0, acc1);
        __syncthreads();

        layer_mm<32>(sm, WP2f, arow, widx, acc0, acc1);   // K=128
        __syncthreads();
        epi(sm, B2f, arow, jcol, acc0, acc1);
        __syncthreads();

        layer_mm<32>(sm, WP3f, arow, widx, acc0, acc1);   // K=128

        // ---- head: tanh, dot with W4, lane-reduce, cross-half combine ----
        {
            float2 w4 = *(const float2*)(sm + W4f + jcol);
            float2 b3v = *(const float2*)(sm + B3f + jcol);
            float s[8];
            #pragma unroll
            for (int e = 0; e < 8; e++) {
                float2 p0 = unpack2(acc0[e]);
                float2 p1 = unpack2(acc1[e]);
                float t0 = tanh_fast(p0.x + p0.y + b3v.x);
                float t1 = tanh_fast(p1.x + p1.y + b3v.y);
                s[e] = fmaf(w4.x, t0, w4.y * t1);
            }
            #pragma unroll
            for (int st = 16; st; st >>= 1)
                #pragma unroll
                for (int e = 0; e < 8; e++)
                    s[e] += __shfl_xor_sync(0xFFFFFFFFu, s[e], st);
            if (lane == 0) {
                #pragma unroll
                for (int e = 0; e < 8; e++)
                    sm[PPf + (eb + e) * 2 + h] = s[e];
            }
        }
        __syncthreads();
        if (tid < 64) {
            int eg = tbase + tid;
            if (eg < E)
                out[eg] = sigmoid_fast(sm[PPf + 2 * tid] + sm[PPf + 2 * tid + 1] + b4s);
        }
    }
}

extern "C" void kernel_launch(void* const* d_in, const int* in_sizes, int n_in,
                              void* d_out, int out_size)
{
    // metadata order: x, edge_index, edge_attr, W1, b1, W2, b2, W3, b3, W4, b4
    const float* EA = (const float*)d_in[2];
    const float* W1 = (const float*)d_in[3];
    const float* b1 = (const float*)d_in[4];
    const float* W2 = (const float*)d_in[5];
    const float* b2 = (const float*)d_in[6];
    const float* W3 = (const float*)d_in[7];
    const float* b3 = (const float*)d_in[8];
    const float* W4 = (const float*)d_in[9];
    const float* b4 = (const float*)d_in[10];
    float* out = (float*)d_out;
    const int E = out_size;   // 800000

    cudaFuncSetAttribute(gnn_mlp_v3,
                         cudaFuncAttributeMaxDynamicSharedMemorySize, SMEM_BYTES);
    int nsm = 148;
    cudaDeviceGetAttribute(&nsm, cudaDevAttrMultiProcessorCount, 0);

    gnn_mlp_v3<<<nsm, NTHREADS, SMEM_BYTES>>>(
        EA, W1, b1, W2, b2, W3, b3, W4, b4, out, E);
}